// round 11
// baseline (speedup 1.0000x reference)
#include <cuda_runtime.h>
#include <math.h>
#include <stdint.h>

// GeometricFeatureExtractor: coords (N,3) f32 -> angles (N,3) + frames (N,3,3)
// Output layout: [angles (3N floats)][frames (9N floats)].
//
// 4 consecutive rows per thread, per-warp 128-row sub-tiles with warp-local
// shared staging (__syncwarp only). 64-thread blocks so occupancy is
// register-limited (~40 warps/SM) instead of smem-limited. Streaming cache
// hints on all global traffic. Edge blocks: scalar fallback.

#define THREADS 64
#define ROWS 4
#define WTILE 128               // rows per warp (32 lanes * 4 rows)
#define TILE (THREADS * ROWS)   // 256 rows per block

__device__ __forceinline__ void compute_row(
    float v1x, float v1y, float v1z,
    float v2x, float v2y, float v2z,
    float* __restrict__ fr9, float& ang)
{
    float dot = v1x * v2x + v1y * v2y + v1z * v2z;
    float cosang = fminf(1.0f, fmaxf(-1.0f, dot));
    ang = acosf(cosang);

    float ux = v2x - dot * v1x;
    float uy = v2y - dot * v1y;
    float uz = v2z - dot * v1z;
    float nu = sqrtf(ux * ux + uy * uy + uz * uz) + 1e-10f;
    float ru = __fdividef(1.0f, nu);
    float e2x = ux * ru, e2y = uy * ru, e2z = uz * ru;

    fr9[0] = v1x; fr9[1] = v1y; fr9[2] = v1z;
    fr9[3] = e2x; fr9[4] = e2y; fr9[5] = e2z;
    fr9[6] = v1y * e2z - v1z * e2y;
    fr9[7] = v1z * e2x - v1x * e2z;
    fr9[8] = v1x * e2y - v1y * e2x;
}

__global__ __launch_bounds__(THREADS) void geo_kernel(
    const float* __restrict__ coords,
    float* __restrict__ angles,
    float* __restrict__ frames,
    int n)
{
    __shared__ alignas(16) float s_fr[TILE * 9];   // 9216 B
    __shared__ alignas(16) float s_ang[TILE];      // 1024 B

    const int base = blockIdx.x * TILE;
    const int tid  = threadIdx.x;
    const int w    = tid >> 5;
    const int lane = tid & 31;

    const bool interior = (base >= 1) && (base <= n - TILE - 2);

    if (interior) {
        const int wbase = base + w * WTILE;

        // ---- load 6 coord rows (wbase+4*lane-1 .. +4) via 5 LDG.128 ----
        // float index 3*wbase + 12*lane - 4 is divisible by 4 (wbase % 4 == 0).
        alignas(16) float in[20];
        const float4* g4 = (const float4*)(coords + (3 * (size_t)wbase + 12 * lane - 4));
        #pragma unroll
        for (int j = 0; j < 5; ++j) ((float4*)in)[j] = __ldcs(g4 + j);

        // ---- 5 shared normalized difference vectors ----
        float vx[5], vy[5], vz[5];
        #pragma unroll
        for (int j = 0; j < 5; ++j) {
            float dx = in[3 * j + 4] - in[3 * j + 1];
            float dy = in[3 * j + 5] - in[3 * j + 2];
            float dz = in[3 * j + 6] - in[3 * j + 3];
            float nn = sqrtf(dx * dx + dy * dy + dz * dz) + 1e-10f;
            float r  = __fdividef(1.0f, nn);
            vx[j] = dx * r; vy[j] = dy * r; vz[j] = dz * r;
        }

        // ---- 4 rows: row k uses (v[k], v[k+1]) ----
        alignas(16) float fr[36];
        float a[4];
        #pragma unroll
        for (int k = 0; k < 4; ++k)
            compute_row(vx[k], vy[k], vz[k], vx[k + 1], vy[k + 1], vz[k + 1],
                        fr + 9 * k, a[k]);

        // ---- warp-local shared staging ----
        float* sfr_w  = s_fr + (size_t)w * WTILE * 9;
        float* sang_w = s_ang + w * WTILE;

        float4* sfr = (float4*)(sfr_w + 36 * lane);
        #pragma unroll
        for (int q = 0; q < 9; ++q) sfr[q] = ((float4*)fr)[q];
        ((float4*)(sang_w + 4 * lane))[0] = make_float4(a[0], a[1], a[2], a[3]);

        __syncwarp();

        // ---- coalesced streaming copy-out (warp covers its own 128 rows) ----
        float4* fout = (float4*)(frames + 9 * (size_t)wbase);
        const float4* sf = (const float4*)sfr_w;
        #pragma unroll
        for (int k = 0; k < 9; ++k) {           // 9*32 = 288 = WTILE*9/4 exactly
            int v = lane + 32 * k;
            __stcs(fout + v, sf[v]);
        }

        float4* aout = (float4*)(angles + 3 * (size_t)wbase);
        #pragma unroll
        for (int k = 0; k < 3; ++k) {           // 3*32 = 96 = WTILE*3/4 exactly
            int v = lane + 32 * k;
            int j = 4 * v;
            float4 av;
            av.x = sang_w[(j + 0) / 3];
            av.y = sang_w[(j + 1) / 3];
            av.z = sang_w[(j + 2) / 3];
            av.w = sang_w[(j + 3) / 3];
            __stcs(aout + v, av);
        }
    } else {
        // ---- generic scalar path (first/last blocks only) ----
        for (int lr = tid; lr < TILE; lr += THREADS) {
            int i = base + lr;
            if (i >= n) break;
            int c = min(max(i, 1), n - 2);
            const float* p = coords + 3 * (size_t)(c - 1);
            float ax = p[0], ay = p[1], az = p[2];
            float bx = p[3], by = p[4], bz = p[5];
            float cx = p[6], cy = p[7], cz = p[8];

            float d1x = bx - ax, d1y = by - ay, d1z = bz - az;
            float d2x = cx - bx, d2y = cy - by, d2z = cz - bz;

            float n1 = sqrtf(d1x * d1x + d1y * d1y + d1z * d1z) + 1e-10f;
            float r1 = __fdividef(1.0f, n1);
            float v1x = d1x * r1, v1y = d1y * r1, v1z = d1z * r1;

            float n2 = sqrtf(d2x * d2x + d2y * d2y + d2z * d2z) + 1e-10f;
            float r2 = __fdividef(1.0f, n2);
            float v2x = d2x * r2, v2y = d2y * r2, v2z = d2z * r2;

            float fr9[9]; float ang;
            compute_row(v1x, v1y, v1z, v2x, v2y, v2z, fr9, ang);

            float aval = (i == 0 || i == n - 1) ? 0.0f : ang;
            float* ar = angles + 3 * (size_t)i;
            ar[0] = aval; ar[1] = aval; ar[2] = aval;
            float* f = frames + 9 * (size_t)i;
            #pragma unroll
            for (int q = 0; q < 9; ++q) f[q] = fr9[q];
        }
    }
}

extern "C" void kernel_launch(void* const* d_in, const int* in_sizes, int n_in,
                              void* d_out, int out_size)
{
    const float* coords = (const float*)d_in[0];
    int n = in_sizes[0] / 3;

    float* angles = (float*)d_out;                  // (N,3)
    float* frames = (float*)d_out + 3 * (size_t)n;  // (N,3,3)

    int blocks = (n + TILE - 1) / TILE;
    geo_kernel<<<blocks, THREADS>>>(coords, angles, frames, n);
}

// round 12
// speedup vs baseline: 1.0261x; 1.0261x over previous
#include <cuda_runtime.h>
#include <math.h>
#include <stdint.h>

// GeometricFeatureExtractor: coords (N,3) f32 -> angles (N,3) + frames (N,3,3)
// Output layout: [angles (3N floats)][frames (9N floats)].
//
// 4 consecutive rows per thread, per-warp 128-row sub-tiles. Frames staged in
// warp-local shared (conflict-free STS.128 / LDS.128) and streamed out as
// float4; angles expanded x3 in registers and stored directly (contiguous,
// 16B-aligned per thread). __syncwarp only. Edge blocks: scalar fallback.

#define THREADS 128
#define ROWS 4
#define WTILE 128               // rows per warp (32 lanes * 4 rows)
#define TILE (THREADS * ROWS)   // 512 rows per block

__device__ __forceinline__ void compute_row(
    float v1x, float v1y, float v1z,
    float v2x, float v2y, float v2z,
    float* __restrict__ fr9, float& ang)
{
    float dot = v1x * v2x + v1y * v2y + v1z * v2z;
    float cosang = fminf(1.0f, fmaxf(-1.0f, dot));
    ang = acosf(cosang);

    float ux = v2x - dot * v1x;
    float uy = v2y - dot * v1y;
    float uz = v2z - dot * v1z;
    float nu = sqrtf(ux * ux + uy * uy + uz * uz) + 1e-10f;
    float ru = __fdividef(1.0f, nu);
    float e2x = ux * ru, e2y = uy * ru, e2z = uz * ru;

    fr9[0] = v1x; fr9[1] = v1y; fr9[2] = v1z;
    fr9[3] = e2x; fr9[4] = e2y; fr9[5] = e2z;
    fr9[6] = v1y * e2z - v1z * e2y;
    fr9[7] = v1z * e2x - v1x * e2z;
    fr9[8] = v1x * e2y - v1y * e2x;
}

__global__ __launch_bounds__(THREADS) void geo_kernel(
    const float* __restrict__ coords,
    float* __restrict__ angles,
    float* __restrict__ frames,
    int n)
{
    __shared__ alignas(16) float s_fr[TILE * 9];   // 18432 B (frames only)

    const int base = blockIdx.x * TILE;
    const int tid  = threadIdx.x;
    const int w    = tid >> 5;
    const int lane = tid & 31;

    const bool interior = (base >= 1) && (base <= n - TILE - 2);

    if (interior) {
        const int wbase = base + w * WTILE;

        // ---- load 6 coord rows (wbase+4*lane-1 .. +4) via 5 LDG.128 ----
        // float index 3*wbase + 12*lane - 4 is divisible by 4 (wbase % 4 == 0).
        alignas(16) float in[20];
        const float4* g4 = (const float4*)(coords + (3 * (size_t)wbase + 12 * lane - 4));
        #pragma unroll
        for (int j = 0; j < 5; ++j) ((float4*)in)[j] = __ldcs(g4 + j);

        // ---- 5 shared normalized difference vectors ----
        float vx[5], vy[5], vz[5];
        #pragma unroll
        for (int j = 0; j < 5; ++j) {
            float dx = in[3 * j + 4] - in[3 * j + 1];
            float dy = in[3 * j + 5] - in[3 * j + 2];
            float dz = in[3 * j + 6] - in[3 * j + 3];
            float nn = sqrtf(dx * dx + dy * dy + dz * dz) + 1e-10f;
            float r  = __fdividef(1.0f, nn);
            vx[j] = dx * r; vy[j] = dy * r; vz[j] = dz * r;
        }

        // ---- 4 rows: row k uses (v[k], v[k+1]) ----
        alignas(16) float fr[36];
        float a[4];
        #pragma unroll
        for (int k = 0; k < 4; ++k)
            compute_row(vx[k], vy[k], vz[k], vx[k + 1], vy[k + 1], vz[k + 1],
                        fr + 9 * k, a[k]);

        // ---- angles: expand x3 in registers, store directly ----
        // Thread's 12 angle floats start at 3*wbase + 12*lane (16B-aligned).
        {
            float4* aout = (float4*)(angles + (3 * (size_t)wbase + 12 * lane));
            __stcs(aout + 0, make_float4(a[0], a[0], a[0], a[1]));
            __stcs(aout + 1, make_float4(a[1], a[1], a[2], a[2]));
            __stcs(aout + 2, make_float4(a[2], a[3], a[3], a[3]));
        }

        // ---- frames: warp-local shared staging + coalesced copy-out ----
        float* sfr_w = s_fr + (size_t)w * WTILE * 9;

        float4* sfr = (float4*)(sfr_w + 36 * lane);
        #pragma unroll
        for (int q = 0; q < 9; ++q) sfr[q] = ((float4*)fr)[q];

        __syncwarp();

        float4* fout = (float4*)(frames + 9 * (size_t)wbase);
        const float4* sf = (const float4*)sfr_w;
        #pragma unroll
        for (int k = 0; k < 9; ++k) {           // 9*32 = 288 = WTILE*9/4 exactly
            int v = lane + 32 * k;
            __stcs(fout + v, sf[v]);
        }
    } else {
        // ---- generic scalar path (first/last blocks only) ----
        for (int lr = tid; lr < TILE; lr += THREADS) {
            int i = base + lr;
            if (i >= n) break;
            int c = min(max(i, 1), n - 2);
            const float* p = coords + 3 * (size_t)(c - 1);
            float ax = p[0], ay = p[1], az = p[2];
            float bx = p[3], by = p[4], bz = p[5];
            float cx = p[6], cy = p[7], cz = p[8];

            float d1x = bx - ax, d1y = by - ay, d1z = bz - az;
            float d2x = cx - bx, d2y = cy - by, d2z = cz - bz;

            float n1 = sqrtf(d1x * d1x + d1y * d1y + d1z * d1z) + 1e-10f;
            float r1 = __fdividef(1.0f, n1);
            float v1x = d1x * r1, v1y = d1y * r1, v1z = d1z * r1;

            float n2 = sqrtf(d2x * d2x + d2y * d2y + d2z * d2z) + 1e-10f;
            float r2 = __fdividef(1.0f, n2);
            float v2x = d2x * r2, v2y = d2y * r2, v2z = d2z * r2;

            float fr9[9]; float ang;
            compute_row(v1x, v1y, v1z, v2x, v2y, v2z, fr9, ang);

            float aval = (i == 0 || i == n - 1) ? 0.0f : ang;
            float* ar = angles + 3 * (size_t)i;
            ar[0] = aval; ar[1] = aval; ar[2] = aval;
            float* f = frames + 9 * (size_t)i;
            #pragma unroll
            for (int q = 0; q < 9; ++q) f[q] = fr9[q];
        }
    }
}

extern "C" void kernel_launch(void* const* d_in, const int* in_sizes, int n_in,
                              void* d_out, int out_size)
{
    const float* coords = (const float*)d_in[0];
    int n = in_sizes[0] / 3;

    float* angles = (float*)d_out;                  // (N,3)
    float* frames = (float*)d_out + 3 * (size_t)n;  // (N,3,3)

    int blocks = (n + TILE - 1) / TILE;
    geo_kernel<<<blocks, THREADS>>>(coords, angles, frames, n);
}

// round 14
// speedup vs baseline: 1.0316x; 1.0054x over previous
#include <cuda_runtime.h>
#include <math.h>
#include <stdint.h>

// GeometricFeatureExtractor: coords (N,3) f32 -> angles (N,3) + frames (N,3,3)
// Output layout: [angles (3N floats)][frames (9N floats)].
//
// 4 consecutive rows per thread, per-warp 128-row sub-tiles. Outputs staged in
// warp-local shared (conflict-free STS.128), then written to global by the TMA
// bulk-copy engine (cp.async.bulk shared->global), eliminating all per-lane
// copy-out LDS/STG traffic. __syncwarp only. Edge blocks: scalar fallback.

#define THREADS 128
#define ROWS 4
#define WTILE 128               // rows per warp (32 lanes * 4 rows)
#define TILE (THREADS * ROWS)   // 512 rows per block

__device__ __forceinline__ void compute_row(
    float v1x, float v1y, float v1z,
    float v2x, float v2y, float v2z,
    float* __restrict__ fr9, float& ang)
{
    float dot = v1x * v2x + v1y * v2y + v1z * v2z;
    float cosang = fminf(1.0f, fmaxf(-1.0f, dot));
    ang = acosf(cosang);

    float ux = v2x - dot * v1x;
    float uy = v2y - dot * v1y;
    float uz = v2z - dot * v1z;
    float nu = sqrtf(ux * ux + uy * uy + uz * uz) + 1e-10f;
    float ru = __fdividef(1.0f, nu);
    float e2x = ux * ru, e2y = uy * ru, e2z = uz * ru;

    fr9[0] = v1x; fr9[1] = v1y; fr9[2] = v1z;
    fr9[3] = e2x; fr9[4] = e2y; fr9[5] = e2z;
    fr9[6] = v1y * e2z - v1z * e2y;
    fr9[7] = v1z * e2x - v1x * e2z;
    fr9[8] = v1x * e2y - v1y * e2x;
}

__global__ __launch_bounds__(THREADS) void geo_kernel(
    const float* __restrict__ coords,
    float* __restrict__ angles,
    float* __restrict__ frames,
    int n)
{
    __shared__ alignas(16) float s_fr[TILE * 9];    // 18432 B
    __shared__ alignas(16) float s_ang3[TILE * 3];  //  6144 B (expanded x3)

    const int base = blockIdx.x * TILE;
    const int tid  = threadIdx.x;
    const int w    = tid >> 5;
    const int lane = tid & 31;

    const bool interior = (base >= 1) && (base <= n - TILE - 2);

    if (interior) {
        const int wbase = base + w * WTILE;

        // ---- load 6 coord rows (wbase+4*lane-1 .. +4) via 5 LDG.128 ----
        alignas(16) float in[20];
        const float4* g4 = (const float4*)(coords + (3 * (size_t)wbase + 12 * lane - 4));
        #pragma unroll
        for (int j = 0; j < 5; ++j) ((float4*)in)[j] = __ldcs(g4 + j);

        // ---- 5 shared normalized difference vectors ----
        float vx[5], vy[5], vz[5];
        #pragma unroll
        for (int j = 0; j < 5; ++j) {
            float dx = in[3 * j + 4] - in[3 * j + 1];
            float dy = in[3 * j + 5] - in[3 * j + 2];
            float dz = in[3 * j + 6] - in[3 * j + 3];
            float nn = sqrtf(dx * dx + dy * dy + dz * dz) + 1e-10f;
            float r  = __fdividef(1.0f, nn);
            vx[j] = dx * r; vy[j] = dy * r; vz[j] = dz * r;
        }

        // ---- 4 rows: row k uses (v[k], v[k+1]) ----
        alignas(16) float fr[36];
        float a[4];
        #pragma unroll
        for (int k = 0; k < 4; ++k)
            compute_row(vx[k], vy[k], vz[k], vx[k + 1], vy[k + 1], vz[k + 1],
                        fr + 9 * k, a[k]);

        // ---- stage into warp-local shared ----
        float* sfr_w  = s_fr   + (size_t)w * WTILE * 9;
        float* sang_w = s_ang3 + (size_t)w * WTILE * 3;

        float4* sfr = (float4*)(sfr_w + 36 * lane);   // stride 36 fl: conflict-free
        #pragma unroll
        for (int q = 0; q < 9; ++q) sfr[q] = ((float4*)fr)[q];

        float4* sa = (float4*)(sang_w + 12 * lane);   // stride 12 fl: conflict-free
        sa[0] = make_float4(a[0], a[0], a[0], a[1]);
        sa[1] = make_float4(a[1], a[1], a[2], a[2]);
        sa[2] = make_float4(a[2], a[3], a[3], a[3]);

        // ---- TMA bulk store: shared -> global ----
        asm volatile("fence.proxy.async.shared::cta;" ::: "memory");
        __syncwarp();

        if (lane == 0) {
            uint32_t s_fr_addr  = (uint32_t)__cvta_generic_to_shared(sfr_w);
            uint32_t s_ang_addr = (uint32_t)__cvta_generic_to_shared(sang_w);
            float* fdst = frames + 9 * (size_t)wbase;   // 16B-aligned
            float* adst = angles + 3 * (size_t)wbase;   // 16B-aligned

            asm volatile(
                "cp.async.bulk.global.shared::cta.bulk_group [%0], [%1], %2;"
                :: "l"(fdst), "r"(s_fr_addr), "r"((uint32_t)(WTILE * 9 * 4))
                : "memory");
            asm volatile(
                "cp.async.bulk.global.shared::cta.bulk_group [%0], [%1], %2;"
                :: "l"(adst), "r"(s_ang_addr), "r"((uint32_t)(WTILE * 3 * 4))
                : "memory");
            asm volatile("cp.async.bulk.commit_group;" ::: "memory");
            asm volatile("cp.async.bulk.wait_group 0;" ::: "memory");
        }
    } else {
        // ---- generic scalar path (first/last blocks only) ----
        for (int lr = tid; lr < TILE; lr += THREADS) {
            int i = base + lr;
            if (i >= n) break;
            int c = min(max(i, 1), n - 2);
            const float* p = coords + 3 * (size_t)(c - 1);
            float ax = p[0], ay = p[1], az = p[2];
            float bx = p[3], by = p[4], bz = p[5];
            float cx = p[6], cy = p[7], cz = p[8];

            float d1x = bx - ax, d1y = by - ay, d1z = bz - az;
            float d2x = cx - bx, d2y = cy - by, d2z = cz - bz;

            float n1 = sqrtf(d1x * d1x + d1y * d1y + d1z * d1z) + 1e-10f;
            float r1 = __fdividef(1.0f, n1);
            float v1x = d1x * r1, v1y = d1y * r1, v1z = d1z * r1;

            float n2 = sqrtf(d2x * d2x + d2y * d2y + d2z * d2z) + 1e-10f;
            float r2 = __fdividef(1.0f, n2);
            float v2x = d2x * r2, v2y = d2y * r2, v2z = d2z * r2;

            float fr9[9]; float ang;
            compute_row(v1x, v1y, v1z, v2x, v2y, v2z, fr9, ang);

            float aval = (i == 0 || i == n - 1) ? 0.0f : ang;
            float* ar = angles + 3 * (size_t)i;
            ar[0] = aval; ar[1] = aval; ar[2] = aval;
            float* f = frames + 9 * (size_t)i;
            #pragma unroll
            for (int q = 0; q < 9; ++q) f[q] = fr9[q];
        }
    }
}

extern "C" void kernel_launch(void* const* d_in, const int* in_sizes, int n_in,
                              void* d_out, int out_size)
{
    const float* coords = (const float*)d_in[0];
    int n = in_sizes[0] / 3;

    float* angles = (float*)d_out;                  // (N,3)
    float* frames = (float*)d_out + 3 * (size_t)n;  // (N,3,3)

    int blocks = (n + TILE - 1) / TILE;
    geo_kernel<<<blocks, THREADS>>>(coords, angles, frames, n);
}